// round 2
// baseline (speedup 1.0000x reference)
#include <cuda_runtime.h>
#include <math.h>

// Problem constants
#define BATCH 1024
#define DDIM  64
#define MNUM  3
#define CNUM  16384
#define NBR   2

// Tiling
#define TC   128     // centroid tile (rows)
#define TB   128     // feature tile (cols)
#define PADA 65      // sc row stride (floats)
#define PADB 132     // sfT k-row stride (floats), breaks store-bank alignment

typedef unsigned long long u64;

__device__ __forceinline__ u64 splat2(float v) {
    u64 r; asm("mov.b64 %0, {%1, %1};" : "=l"(r) : "f"(v)); return r;
}
__device__ __forceinline__ u64 ffma2(u64 a, u64 b, u64 c) {
    u64 d; asm("fma.rn.f32x2 %0, %1, %2, %3;" : "=l"(d) : "l"(a), "l"(b), "l"(c)); return d;
}
__device__ __forceinline__ u64 fmul2(u64 a, u64 b) {
    u64 d; asm("mul.rn.f32x2 %0, %1, %2;" : "=l"(d) : "l"(a), "l"(b)); return d;
}
__device__ __forceinline__ u64 fadd2(u64 a, u64 b) {
    u64 d; asm("add.rn.f32x2 %0, %1, %2;" : "=l"(d) : "l"(a), "l"(b)); return d;
}
__device__ __forceinline__ void unpack2(u64 p, float& lo, float& hi) {
    asm("mov.b64 {%0, %1}, %2;" : "=f"(lo), "=f"(hi) : "l"(p));
}

// Scratch: per-(branch,m,b) sum of exp(logit). 2*3*1024 = 6144 floats.
__device__ float g_S[NBR * MNUM * BATCH];

__global__ void init_kernel() {
    int i = blockIdx.x * blockDim.x + threadIdx.x;
    if (i < NBR * MNUM * BATCH) g_S[i] = 0.0f;
}

// Each block: one (branch, m, cTile, bTile). 128x128 dots (D=64) via packed
// FFMA2, exp via FMA-only f32x2 polynomial, reduce over c, atomicAdd per b.
__global__ __launch_bounds__(256, 2)
void gemm_exp_kernel(const float* __restrict__ cen,  const float* __restrict__ cenI,
                     const float* __restrict__ f,    const float* __restrict__ fI,
                     const float* __restrict__ conc, const float* __restrict__ concI)
{
    extern __shared__ float sm[];
    float* sc   = sm;                         // [TC][PADA]  centroid tile (row-major over c)
    float* sfT  = sm + TC * PADA;             // [DDIM][PADB] feature tile, k-major + permuted cols
    float* inv4 = sm + TC * PADA + DDIM * PADB; // [TC] 1/(4*conc)
    float* red  = sm;                         // reduction buffer, aliases sc after sync

    const int cT = blockIdx.x;
    const int bT = blockIdx.y;
    const int z  = blockIdx.z;
    const int branch = (z >= MNUM) ? 1 : 0;
    const int m      = branch ? (z - MNUM) : z;

    // branch 0: loss(M_kmeans, features_I, concentrations)
    // branch 1: loss(M_kmeans_I, features, concentrations_I)
    const float* cenP  = branch ? cenI  : cen;
    const float* featP = branch ? f     : fI;
    const float* concP = branch ? concI : conc;

    const int tid = threadIdx.x;

    const float* gc = cenP  + ((size_t)(m * CNUM + cT * TC)) * DDIM;
    const float* gf = featP + (size_t)bT * TB * DDIM;

    // Load tiles. Centroids: [c][k] row-major (PADA). Features: transposed to
    // sfT[k][perm(c)] where perm(c) = (c%8/2)*32 + (c/8)*2 + (c%2), so that a
    // thread's 4 b-pairs for a given k are 4 conflict-free LDS.64.
    #pragma unroll
    for (int it = 0; it < 8; it++) {
        int q   = tid + 256 * it;          // float4 index, 2048 total per tile
        int row = q >> 4;                  // 0..127
        int d   = (q & 15) << 2;           // 0..60
        float4 v = *(const float4*)(gc + row * DDIM + d);
        float* dc = sc + row * PADA + d;
        dc[0] = v.x; dc[1] = v.y; dc[2] = v.z; dc[3] = v.w;
        float4 w = *(const float4*)(gf + row * DDIM + d);
        int rr = row & 7;
        int pc = (rr >> 1) * 32 + (row >> 3) * 2 + (rr & 1);  // permuted column
        sfT[(d + 0) * PADB + pc] = w.x;
        sfT[(d + 1) * PADB + pc] = w.y;
        sfT[(d + 2) * PADB + pc] = w.z;
        sfT[(d + 3) * PADB + pc] = w.w;
    }
    if (tid < TC) inv4[tid] = 0.25f / concP[m * CNUM + cT * TC + tid];
    __syncthreads();

    const int ty = tid >> 4;   // 0..15 -> c sub-rows ty + 16*i
    const int tx = tid & 15;   // 0..15 -> b cols 8*tx + {0..7}

    u64 acc2[8][4];
    #pragma unroll
    for (int i = 0; i < 8; i++)
        #pragma unroll
        for (int j = 0; j < 4; j++) acc2[i][j] = 0ULL;

    const float* pA  = sc  + ty * PADA;
    const float* pBT = sfT + tx * 2;

    #pragma unroll 8
    for (int k = 0; k < DDIM; k++) {
        u64 b2[4];
        #pragma unroll
        for (int j = 0; j < 4; j++)
            b2[j] = *(const u64*)(pBT + k * PADB + j * 32);
        #pragma unroll
        for (int i = 0; i < 8; i++) {
            u64 a2 = splat2(pA[i * 16 * PADA + k]);
            #pragma unroll
            for (int j = 0; j < 4; j++)
                acc2[i][j] = ffma2(a2, b2[j], acc2[i][j]);
        }
    }

    u64 invr2[8];
    #pragma unroll
    for (int i = 0; i < 8; i++) invr2[i] = splat2(inv4[ty + 16 * i]);

    // exp(z) = (e^{z/4})^4, z/4 in [-0.5,0.5]; degree-6 Taylor, packed f32x2.
    const u64 c6 = splat2(1.0f / 720.0f), c5 = splat2(1.0f / 120.0f);
    const u64 c4 = splat2(1.0f / 24.0f),  c3 = splat2(1.0f / 6.0f);
    const u64 c2 = splat2(0.5f),          one = splat2(1.0f);

    u64 part2[4];
    #pragma unroll
    for (int j = 0; j < 4; j++) part2[j] = 0ULL;

    #pragma unroll
    for (int i = 0; i < 8; i++)
        #pragma unroll
        for (int j = 0; j < 4; j++) {
            u64 x = fmul2(acc2[i][j], invr2[i]);   // dot/(4*conc), packed pair
            u64 p = ffma2(x, c6, c5);
            p = ffma2(x, p, c4);
            p = ffma2(x, p, c3);
            p = ffma2(x, p, c2);
            p = ffma2(x, p, one);
            p = ffma2(x, p, one);
            p = fmul2(p, p);
            p = fmul2(p, p);                        // e^{dot/conc}
            part2[j] = fadd2(part2[j], p);
        }

    __syncthreads();   // tiles no longer needed; red aliases sc
    #pragma unroll
    for (int j = 0; j < 4; j++) {
        float lo, hi;
        unpack2(part2[j], lo, hi);
        red[(8 * tx + 2 * j + 0) * 17 + ty] = lo;
        red[(8 * tx + 2 * j + 1) * 17 + ty] = hi;
    }
    __syncthreads();

    if (tid < TB) {
        float s = 0.0f;
        #pragma unroll
        for (int t = 0; t < 16; t++) s += red[tid * 17 + t];
        atomicAdd(&g_S[(branch * MNUM + m) * BATCH + bT * TB + tid], s);
    }
}

// Single block: positive logits + log(S) + full deterministic reduction + scale.
__global__ void finalize_kernel(const float* __restrict__ cen,  const float* __restrict__ cenI,
                                const float* __restrict__ f,    const float* __restrict__ fI,
                                const float* __restrict__ conc, const float* __restrict__ concI,
                                const int* __restrict__ lab,    const int* __restrict__ labI,
                                const int* __restrict__ lb,     float* __restrict__ out)
{
    __shared__ float sred[1024];
    const int tid = threadIdx.x;
    float acc = 0.0f;

    for (int idx = tid; idx < NBR * MNUM * BATCH; idx += 1024) {
        int branch = idx / (MNUM * BATCH);
        int r = idx - branch * MNUM * BATCH;
        int m = r / BATCH;
        int b = r - m * BATCH;

        const float* cenP  = branch ? cenI  : cen;
        const float* featP = branch ? f     : fI;
        const float* concP = branch ? concI : conc;
        const int*   labP  = branch ? labI  : lab;

        int c = labP[m * BATCH + b];
        const float4* cr = (const float4*)(cenP + ((size_t)(m * CNUM) + c) * DDIM);
        const float4* fr = (const float4*)(featP + (size_t)b * DDIM);
        float dot = 0.0f;
        #pragma unroll
        for (int d = 0; d < 16; d++) {
            float4 a = cr[d];
            float4 w = fr[d];
            dot += a.x * w.x + a.y * w.y + a.z * w.z + a.w * w.w;
        }
        float logit = dot / concP[m * CNUM + c];
        acc += logit - logf(g_S[idx]);       // log(pos/sum) = logit_pos - log(S)
    }

    sred[tid] = acc;
    __syncthreads();
    for (int s = 512; s > 0; s >>= 1) {
        if (tid < s) sred[tid] += sred[tid + s];
        __syncthreads();
    }
    if (tid == 0) {
        // (1/B) * lb * (-1/M) * 0.5 * (t + t_I)
        float scale = -(float)lb[0] / (2.0f * (float)BATCH * (float)MNUM);
        out[0] = scale * sred[0];
    }
}

extern "C" void kernel_launch(void* const* d_in, const int* in_sizes, int n_in,
                              void* d_out, int out_size)
{
    const float* f     = (const float*)d_in[0];
    const float* fI    = (const float*)d_in[1];
    const float* cen   = (const float*)d_in[2];
    const float* cenI  = (const float*)d_in[3];
    const float* conc  = (const float*)d_in[4];
    const float* concI = (const float*)d_in[5];
    const int*   lab   = (const int*)d_in[6];
    const int*   labI  = (const int*)d_in[7];
    const int*   lb    = (const int*)d_in[8];
    float* out = (float*)d_out;

    const int smem_bytes = (TC * PADA + DDIM * PADB + TC) * (int)sizeof(float); // 67,584
    cudaFuncSetAttribute(gemm_exp_kernel,
                         cudaFuncAttributeMaxDynamicSharedMemorySize, smem_bytes);

    init_kernel<<<6, 1024>>>();
    dim3 grid(CNUM / TC, BATCH / TB, NBR * MNUM);
    gemm_exp_kernel<<<grid, 256, smem_bytes>>>(cen, cenI, f, fI, conc, concI);
    finalize_kernel<<<1, 1024>>>(cen, cenI, f, fI, conc, concI, lab, labI, lb, out);
}

// round 4
// speedup vs baseline: 2.4450x; 2.4450x over previous
#include <cuda_runtime.h>
#include <cuda_bf16.h>
#include <math.h>
#include <stdint.h>

// Problem constants
#define BATCH 1024
#define DDIM  64
#define MNUM  3
#define CNUM  16384
#define NBR   2

// GEMM tiling: CTA 128c x 128b, K=64. 8 warps as 2(c) x 4(b), warp tile 64x32.
#define TC 128
#define TB 128
#define PITCH 144           // smem row pitch bytes (64 bf16 + 8 pad) -> 36 banks

// smem layout (bytes)
#define SMEM_A     0                     // 128 * 144 = 18432
#define SMEM_B     (SMEM_A + TC * PITCH) // 18432
#define SMEM_INV   (SMEM_B + TB * PITCH) // 36864: 128 floats
#define SMEM_SACC  (SMEM_INV + 512)      // 37376: 8 warps * 32 floats
#define SMEM_TOTAL 40960

typedef unsigned long long u64;

__device__ __forceinline__ u64 splat2(float v) {
    u64 r; asm("mov.b64 %0, {%1, %1};" : "=l"(r) : "f"(v)); return r;
}
__device__ __forceinline__ u64 pack2(float lo, float hi) {
    u64 r; asm("mov.b64 %0, {%1, %2};" : "=l"(r) : "f"(lo), "f"(hi)); return r;
}
__device__ __forceinline__ u64 ffma2(u64 a, u64 b, u64 c) {
    u64 d; asm("fma.rn.f32x2 %0, %1, %2, %3;" : "=l"(d) : "l"(a), "l"(b), "l"(c)); return d;
}
__device__ __forceinline__ u64 fmul2(u64 a, u64 b) {
    u64 d; asm("mul.rn.f32x2 %0, %1, %2;" : "=l"(d) : "l"(a), "l"(b)); return d;
}
__device__ __forceinline__ u64 fadd2(u64 a, u64 b) {
    u64 d; asm("add.rn.f32x2 %0, %1, %2;" : "=l"(d) : "l"(a), "l"(b)); return d;
}
__device__ __forceinline__ uint32_t bf2(float lo, float hi) {
    uint32_t r; asm("cvt.rn.bf16x2.f32 %0, %1, %2;" : "=r"(r) : "f"(hi), "f"(lo)); return r;
}
__device__ __forceinline__ uint32_t smem_u32(const void* p) {
    uint32_t a;
    asm("{ .reg .u64 t; cvta.to.shared.u64 t, %1; cvt.u32.u64 %0, t; }" : "=r"(a) : "l"(p));
    return a;
}
__device__ __forceinline__ u64 shfl_xor2(u64 v, int mask) {
    uint32_t lo = (uint32_t)v, hi = (uint32_t)(v >> 32);
    lo = __shfl_xor_sync(0xffffffffu, lo, mask);
    hi = __shfl_xor_sync(0xffffffffu, hi, mask);
    return ((u64)hi << 32) | (u64)lo;
}

#define LDSM4(r, addr)                                                              \
    asm volatile("ldmatrix.sync.aligned.m8n8.x4.shared.b16 {%0,%1,%2,%3}, [%4];"    \
        : "=r"((r)[0]), "=r"((r)[1]), "=r"((r)[2]), "=r"((r)[3]) : "r"(addr))

#define MMA16816(c, a, b)                                                           \
    asm volatile("mma.sync.aligned.m16n8k16.row.col.f32.bf16.bf16.f32 "             \
        "{%0,%1,%2,%3}, {%4,%5,%6,%7}, {%8,%9}, {%0,%1,%2,%3};"                     \
        : "+f"((c)[0]), "+f"((c)[1]), "+f"((c)[2]), "+f"((c)[3])                    \
        : "r"((a)[0]), "r"((a)[1]), "r"((a)[2]), "r"((a)[3]), "r"((b)[0]), "r"((b)[1]))

// bf16 copies of operands (conversion pre-pass). branch 0 uses (cen, feats_I),
// branch 1 uses (cen_I, feats).
__device__ __align__(16) __nv_bfloat16 g_cenb[NBR * MNUM * CNUM * DDIM];
__device__ __align__(16) __nv_bfloat16 g_featb[NBR * BATCH * DDIM];

// Scratch: per-(branch,m,b) sum of exp(logit). 2*3*1024 = 6144 floats.
__device__ float g_S[NBR * MNUM * BATCH];

__global__ void init_kernel() {
    int i = blockIdx.x * blockDim.x + threadIdx.x;
    if (i < NBR * MNUM * BATCH) g_S[i] = 0.0f;
}

#define CEN4  (MNUM * CNUM * (DDIM / 4))   // float4s per branch of centroids
#define FEAT4 (BATCH * (DDIM / 4))

__global__ void convert_kernel(const float* __restrict__ cen, const float* __restrict__ cenI,
                               const float* __restrict__ f,   const float* __restrict__ fI)
{
    int idx = blockIdx.x * blockDim.x + threadIdx.x;
    if (idx < 2 * CEN4) {
        int branch = idx / CEN4, r = idx - branch * CEN4;
        const float4 v = ((const float4*)(branch ? cenI : cen))[r];
        uint2 p; p.x = bf2(v.x, v.y); p.y = bf2(v.z, v.w);
        ((uint2*)g_cenb)[branch * CEN4 + r] = p;
    } else if (idx < 2 * CEN4 + 2 * FEAT4) {
        int t = idx - 2 * CEN4;
        int branch = t / FEAT4, r = t - branch * FEAT4;
        const float4 v = ((const float4*)(branch ? f : fI))[r];   // branch0 -> feats_I
        uint2 p; p.x = bf2(v.x, v.y); p.y = bf2(v.z, v.w);
        ((uint2*)g_featb)[branch * FEAT4 + r] = p;
    }
}

// One CTA: (branch,m,cT,bT). HMMA mma.sync GEMM + packed-f32x2 exp epilogue.
__global__ __launch_bounds__(256, 2)
void mma_exp_kernel(const float* __restrict__ conc, const float* __restrict__ concI)
{
    extern __shared__ char smem[];
    const uint32_t sb = smem_u32(smem);
    const int tid = threadIdx.x;
    const int wid = tid >> 5, lane = tid & 31;
    const int wc = wid >> 2, wb = wid & 3;          // warp grid 2(c) x 4(b)
    const int g = lane >> 2;                        // row group 0..7

    const int cT = blockIdx.x, bT = blockIdx.y, z = blockIdx.z;
    const int branch = (z >= MNUM) ? 1 : 0;
    const int m      = branch ? (z - MNUM) : z;
    const float* concP = branch ? concI : conc;

    // ---- load bf16 tiles into padded smem (rows 128B data + 16B pad) ----
    const uint4* gA = (const uint4*)(g_cenb + ((size_t)(branch * MNUM + m) * CNUM + cT * TC) * DDIM);
    const uint4* gB = (const uint4*)(g_featb + ((size_t)branch * BATCH + bT * TB) * DDIM);
    #pragma unroll
    for (int it = 0; it < 4; it++) {            // 1024 uint4 per tile
        int q = tid + 256 * it;
        int row = q >> 3, seg = q & 7;          // 8 x 16B per row
        *(uint4*)(smem + SMEM_A + row * PITCH + seg * 16) = gA[q];
        *(uint4*)(smem + SMEM_B + row * PITCH + seg * 16) = gB[q];
    }
    if (tid < TC)
        ((float*)(smem + SMEM_INV))[tid] = 0.25f / concP[m * CNUM + cT * TC + tid];
    __syncthreads();

    // ---- GEMM: warp tile 64x32, 4 k-steps of 16 ----
    float c[4][4][4];
    #pragma unroll
    for (int i = 0; i < 4; i++)
        #pragma unroll
        for (int j = 0; j < 4; j++)
            #pragma unroll
            for (int r = 0; r < 4; r++) c[i][j][r] = 0.0f;

    // ldmatrix lane addresses (see fragment mapping):
    // A sub0..3 = rows (m..m+7), (m+8..m+15) at k0, then same at k0+8
    const uint32_t aAddr = sb + SMEM_A + (64 * wc + (lane & 15)) * PITCH + ((lane & 16) ? 16 : 0);
    // B sub0..3 = n rows (n0..n0+7)@k0, (n0..n0+7)@k0+8, (n0+8..n0+15)@k0, @k0+8
    const uint32_t bAddr = sb + SMEM_B + (32 * wb + (lane & 7) + ((lane & 16) ? 8 : 0)) * PITCH
                              + ((lane & 8) ? 16 : 0);

    #pragma unroll
    for (int ks = 0; ks < 4; ks++) {
        uint32_t a[4][4];
        #pragma unroll
        for (int i = 0; i < 4; i++)
            LDSM4(a[i], aAddr + i * (16 * PITCH) + ks * 32);
        uint32_t b0[4], b1[4];
        LDSM4(b0, bAddr + ks * 32);                 // n-tiles 0,1: {b0t0,b1t0,b0t1,b1t1}
        LDSM4(b1, bAddr + 16 * PITCH + ks * 32);    // n-tiles 2,3
        uint32_t bb[4][2] = {{b0[0], b0[1]}, {b0[2], b0[3]}, {b1[0], b1[1]}, {b1[2], b1[3]}};
        #pragma unroll
        for (int i = 0; i < 4; i++)
            #pragma unroll
            for (int j = 0; j < 4; j++)
                MMA16816(c[i][j], a[i], bb[j]);
    }

    // ---- epilogue: exp( dot / conc ) with packed f32x2, reduce over c-rows ----
    const float* invc = (const float*)(smem + SMEM_INV);
    const u64 k6 = splat2(1.0f/720.0f), k5 = splat2(1.0f/120.0f);
    const u64 k4 = splat2(1.0f/24.0f),  k3 = splat2(1.0f/6.0f);
    const u64 k2 = splat2(0.5f),        one = splat2(1.0f);

    u64 colsum[4];
    #pragma unroll
    for (int j = 0; j < 4; j++) colsum[j] = 0ULL;

    #pragma unroll
    for (int i = 0; i < 4; i++) {
        const u64 iq0 = splat2(invc[64 * wc + 16 * i + g]);       // row r0
        const u64 iq1 = splat2(invc[64 * wc + 16 * i + g + 8]);   // row r0+8
        #pragma unroll
        for (int j = 0; j < 4; j++) {
            #pragma unroll
            for (int h = 0; h < 2; h++) {
                u64 pr = pack2(c[i][j][2 * h], c[i][j][2 * h + 1]);
                u64 x = fmul2(pr, h ? iq1 : iq0);   // dot/(4*conc), in [-0.55,0.55]
                u64 p = ffma2(x, k6, k5);
                p = ffma2(x, p, k4);
                p = ffma2(x, p, k3);
                p = ffma2(x, p, k2);
                p = ffma2(x, p, one);
                p = ffma2(x, p, one);
                p = fmul2(p, p);
                p = fmul2(p, p);                    // e^{dot/conc}
                colsum[j] = fadd2(colsum[j], p);
            }
        }
    }
    // butterfly over the 8 row-groups (lanes with equal lane%4)
    #pragma unroll
    for (int mask = 4; mask <= 16; mask <<= 1)
        #pragma unroll
        for (int j = 0; j < 4; j++)
            colsum[j] = fadd2(colsum[j], shfl_xor2(colsum[j], mask));

    float* sacc = (float*)(smem + SMEM_SACC);
    if (lane < 4) {
        #pragma unroll
        for (int j = 0; j < 4; j++) {
            float2 v; v.x = __uint_as_float((uint32_t)colsum[j]);
            v.y = __uint_as_float((uint32_t)(colsum[j] >> 32));
            *(float2*)&sacc[wid * 32 + 8 * j + 2 * lane] = v;     // cols (2*lane, +1) of n-tile j
        }
    }
    __syncthreads();

    if (tid < TB) {
        int wb2 = tid >> 5, lc = tid & 31;
        float s = sacc[wb2 * 32 + lc] + sacc[(wb2 + 4) * 32 + lc];   // wc=0 + wc=1
        atomicAdd(&g_S[z * BATCH + bT * TB + tid], s);
    }
}

// Single block: positive logits + log(S) + deterministic reduction + scale.
__global__ void finalize_kernel(const float* __restrict__ cen,  const float* __restrict__ cenI,
                                const float* __restrict__ f,    const float* __restrict__ fI,
                                const float* __restrict__ conc, const float* __restrict__ concI,
                                const int* __restrict__ lab,    const int* __restrict__ labI,
                                const int* __restrict__ lb,     float* __restrict__ out)
{
    __shared__ float sred[1024];
    const int tid = threadIdx.x;
    float acc = 0.0f;

    for (int idx = tid; idx < NBR * MNUM * BATCH; idx += 1024) {
        int branch = idx / (MNUM * BATCH);
        int r = idx - branch * MNUM * BATCH;
        int m = r / BATCH;
        int b = r - m * BATCH;

        const float* cenP  = branch ? cenI  : cen;
        const float* featP = branch ? f     : fI;
        const float* concP = branch ? concI : conc;
        const int*   labP  = branch ? labI  : lab;

        int cidx = labP[m * BATCH + b];
        const float4* cr = (const float4*)(cenP + ((size_t)(m * CNUM) + cidx) * DDIM);
        const float4* fr = (const float4*)(featP + (size_t)b * DDIM);
        float dot = 0.0f;
        #pragma unroll
        for (int d = 0; d < 16; d++) {
            float4 a = cr[d];
            float4 w = fr[d];
            dot += a.x * w.x + a.y * w.y + a.z * w.z + a.w * w.w;
        }
        float logit = dot / concP[m * CNUM + cidx];
        acc += logit - logf(g_S[idx]);       // log(pos/sum) = logit_pos - log(S)
    }

    sred[tid] = acc;
    __syncthreads();
    for (int s = 512; s > 0; s >>= 1) {
        if (tid < s) sred[tid] += sred[tid + s];
        __syncthreads();
    }
    if (tid == 0) {
        float scale = -(float)lb[0] / (2.0f * (float)BATCH * (float)MNUM);
        out[0] = scale * sred[0];
    }
}

extern "C" void kernel_launch(void* const* d_in, const int* in_sizes, int n_in,
                              void* d_out, int out_size)
{
    const float* f     = (const float*)d_in[0];
    const float* fI    = (const float*)d_in[1];
    const float* cen   = (const float*)d_in[2];
    const float* cenI  = (const float*)d_in[3];
    const float* conc  = (const float*)d_in[4];
    const float* concI = (const float*)d_in[5];
    const int*   lab   = (const int*)d_in[6];
    const int*   labI  = (const int*)d_in[7];
    const int*   lb    = (const int*)d_in[8];
    float* out = (float*)d_out;

    int convN = 2 * CEN4 + 2 * FEAT4;
    convert_kernel<<<(convN + 255) / 256, 256>>>(cen, cenI, f, fI);
    init_kernel<<<6, 1024>>>();
    dim3 grid(CNUM / TC, BATCH / TB, NBR * MNUM);
    mma_exp_kernel<<<grid, 256, SMEM_TOTAL>>>(conc, concI);
    finalize_kernel<<<1, 1024>>>(cen, cenI, f, fI, conc, concI, lab, labI, lb, out);
}

// round 5
// speedup vs baseline: 5.2212x; 2.1354x over previous
#include <cuda_runtime.h>
#include <cuda_bf16.h>
#include <math.h>
#include <stdint.h>

// Problem constants
#define BATCH 1024
#define DDIM  64
#define MNUM  3
#define CNUM  16384
#define NBR   2

// GEMM tiling: CTA 128c x 128b, K=64. 8 warps as 2(c) x 4(b), warp tile 64x32.
#define TC 128
#define TB 128
#define PITCH 144           // smem row pitch bytes (64 bf16 + 8 pad) -> 36 banks

// smem layout (bytes)
#define SMEM_A     0                     // 128 * 144 = 18432
#define SMEM_B     (SMEM_A + TC * PITCH) // 18432
#define SMEM_INV   (SMEM_B + TB * PITCH) // 36864: 128 floats
#define SMEM_SACC  (SMEM_INV + 512)      // 37376: 8 warps * 32 floats
#define SMEM_TOTAL 40960

// finalize pass-1 grid
#define FIN_BLOCKS 24
#define FIN_THREADS 256

typedef unsigned long long u64;

__device__ __forceinline__ u64 splat2(float v) {
    u64 r; asm("mov.b64 %0, {%1, %1};" : "=l"(r) : "f"(v)); return r;
}
__device__ __forceinline__ u64 pack2(float lo, float hi) {
    u64 r; asm("mov.b64 %0, {%1, %2};" : "=l"(r) : "f"(lo), "f"(hi)); return r;
}
__device__ __forceinline__ u64 ffma2(u64 a, u64 b, u64 c) {
    u64 d; asm("fma.rn.f32x2 %0, %1, %2, %3;" : "=l"(d) : "l"(a), "l"(b), "l"(c)); return d;
}
__device__ __forceinline__ u64 fmul2(u64 a, u64 b) {
    u64 d; asm("mul.rn.f32x2 %0, %1, %2;" : "=l"(d) : "l"(a), "l"(b)); return d;
}
__device__ __forceinline__ u64 fadd2(u64 a, u64 b) {
    u64 d; asm("add.rn.f32x2 %0, %1, %2;" : "=l"(d) : "l"(a), "l"(b)); return d;
}
__device__ __forceinline__ uint32_t bf2(float lo, float hi) {
    uint32_t r; asm("cvt.rn.bf16x2.f32 %0, %1, %2;" : "=r"(r) : "f"(hi), "f"(lo)); return r;
}
__device__ __forceinline__ uint32_t smem_u32(const void* p) {
    uint32_t a;
    asm("{ .reg .u64 t; cvta.to.shared.u64 t, %1; cvt.u32.u64 %0, t; }" : "=r"(a) : "l"(p));
    return a;
}
__device__ __forceinline__ u64 shfl_xor2(u64 v, int mask) {
    uint32_t lo = (uint32_t)v, hi = (uint32_t)(v >> 32);
    lo = __shfl_xor_sync(0xffffffffu, lo, mask);
    hi = __shfl_xor_sync(0xffffffffu, hi, mask);
    return ((u64)hi << 32) | (u64)lo;
}

#define LDSM4(r, addr)                                                              \
    asm volatile("ldmatrix.sync.aligned.m8n8.x4.shared.b16 {%0,%1,%2,%3}, [%4];"    \
        : "=r"((r)[0]), "=r"((r)[1]), "=r"((r)[2]), "=r"((r)[3]) : "r"(addr))

#define MMA16816(c, a, b)                                                           \
    asm volatile("mma.sync.aligned.m16n8k16.row.col.f32.bf16.bf16.f32 "             \
        "{%0,%1,%2,%3}, {%4,%5,%6,%7}, {%8,%9}, {%0,%1,%2,%3};"                     \
        : "+f"((c)[0]), "+f"((c)[1]), "+f"((c)[2]), "+f"((c)[3])                    \
        : "r"((a)[0]), "r"((a)[1]), "r"((a)[2]), "r"((a)[3]), "r"((b)[0]), "r"((b)[1]))

// bf16 copies of operands (conversion pre-pass). branch 0 uses (cen, feats_I),
// branch 1 uses (cen_I, feats).
__device__ __align__(16) __nv_bfloat16 g_cenb[NBR * MNUM * CNUM * DDIM];
__device__ __align__(16) __nv_bfloat16 g_featb[NBR * BATCH * DDIM];

// Scratch: per-(branch,m,b) sum of exp(logit). 2*3*1024 = 6144 floats.
__device__ float g_S[NBR * MNUM * BATCH];
// finalize pass-1 block partials
__device__ float g_part[FIN_BLOCKS];

#define CEN4  (MNUM * CNUM * (DDIM / 4))   // float4s per branch of centroids
#define FEAT4 (BATCH * (DDIM / 4))

__global__ void convert_kernel(const float* __restrict__ cen, const float* __restrict__ cenI,
                               const float* __restrict__ f,   const float* __restrict__ fI)
{
    int idx = blockIdx.x * blockDim.x + threadIdx.x;
    if (idx < NBR * MNUM * BATCH) g_S[idx] = 0.0f;   // init merged here
    if (idx < 2 * CEN4) {
        int branch = idx / CEN4, r = idx - branch * CEN4;
        const float4 v = ((const float4*)(branch ? cenI : cen))[r];
        uint2 p; p.x = bf2(v.x, v.y); p.y = bf2(v.z, v.w);
        ((uint2*)g_cenb)[branch * CEN4 + r] = p;
    } else if (idx < 2 * CEN4 + 2 * FEAT4) {
        int t = idx - 2 * CEN4;
        int branch = t / FEAT4, r = t - branch * FEAT4;
        const float4 v = ((const float4*)(branch ? f : fI))[r];   // branch0 -> feats_I
        uint2 p; p.x = bf2(v.x, v.y); p.y = bf2(v.z, v.w);
        ((uint2*)g_featb)[branch * FEAT4 + r] = p;
    }
}

// One CTA: (branch,m,cT,bT). HMMA mma.sync GEMM + packed-f32x2 exp epilogue.
__global__ __launch_bounds__(256, 2)
void mma_exp_kernel(const float* __restrict__ conc, const float* __restrict__ concI)
{
    extern __shared__ char smem[];
    const uint32_t sb = smem_u32(smem);
    const int tid = threadIdx.x;
    const int wid = tid >> 5, lane = tid & 31;
    const int wc = wid >> 2, wb = wid & 3;          // warp grid 2(c) x 4(b)
    const int g = lane >> 2;                        // row group 0..7

    const int cT = blockIdx.x, bT = blockIdx.y, z = blockIdx.z;
    const int branch = (z >= MNUM) ? 1 : 0;
    const int m      = branch ? (z - MNUM) : z;
    const float* concP = branch ? concI : conc;

    // ---- load bf16 tiles into padded smem (rows 128B data + 16B pad) ----
    const uint4* gA = (const uint4*)(g_cenb + ((size_t)(branch * MNUM + m) * CNUM + cT * TC) * DDIM);
    const uint4* gB = (const uint4*)(g_featb + ((size_t)branch * BATCH + bT * TB) * DDIM);
    #pragma unroll
    for (int it = 0; it < 4; it++) {            // 1024 uint4 per tile
        int q = tid + 256 * it;
        int row = q >> 3, seg = q & 7;          // 8 x 16B per row
        *(uint4*)(smem + SMEM_A + row * PITCH + seg * 16) = gA[q];
        *(uint4*)(smem + SMEM_B + row * PITCH + seg * 16) = gB[q];
    }
    if (tid < TC)
        ((float*)(smem + SMEM_INV))[tid] = 0.25f / concP[m * CNUM + cT * TC + tid];
    __syncthreads();

    // ---- GEMM: warp tile 64x32, 4 k-steps of 16 ----
    float c[4][4][4];
    #pragma unroll
    for (int i = 0; i < 4; i++)
        #pragma unroll
        for (int j = 0; j < 4; j++)
            #pragma unroll
            for (int r = 0; r < 4; r++) c[i][j][r] = 0.0f;

    // A sub0..3 = rows (m..m+7), (m+8..m+15) at k0, then same at k0+8
    const uint32_t aAddr = sb + SMEM_A + (64 * wc + (lane & 15)) * PITCH + ((lane & 16) ? 16 : 0);
    // B sub0..3 = n rows (n0..n0+7)@k0, (n0..n0+7)@k0+8, (n0+8..n0+15)@k0, @k0+8
    const uint32_t bAddr = sb + SMEM_B + (32 * wb + (lane & 7) + ((lane & 16) ? 8 : 0)) * PITCH
                              + ((lane & 8) ? 16 : 0);

    #pragma unroll
    for (int ks = 0; ks < 4; ks++) {
        uint32_t a[4][4];
        #pragma unroll
        for (int i = 0; i < 4; i++)
            LDSM4(a[i], aAddr + i * (16 * PITCH) + ks * 32);
        uint32_t b0[4], b1[4];
        LDSM4(b0, bAddr + ks * 32);                 // n-tiles 0,1
        LDSM4(b1, bAddr + 16 * PITCH + ks * 32);    // n-tiles 2,3
        uint32_t bb[4][2] = {{b0[0], b0[1]}, {b0[2], b0[3]}, {b1[0], b1[1]}, {b1[2], b1[3]}};
        #pragma unroll
        for (int i = 0; i < 4; i++)
            #pragma unroll
            for (int j = 0; j < 4; j++)
                MMA16816(c[i][j], a[i], bb[j]);
    }

    // ---- epilogue: exp( dot / conc ) with packed f32x2, reduce over c-rows ----
    const float* invc = (const float*)(smem + SMEM_INV);
    const u64 k6 = splat2(1.0f/720.0f), k5 = splat2(1.0f/120.0f);
    const u64 k4 = splat2(1.0f/24.0f),  k3 = splat2(1.0f/6.0f);
    const u64 k2 = splat2(0.5f),        one = splat2(1.0f);

    u64 colsum[4];
    #pragma unroll
    for (int j = 0; j < 4; j++) colsum[j] = 0ULL;

    #pragma unroll
    for (int i = 0; i < 4; i++) {
        const u64 iq0 = splat2(invc[64 * wc + 16 * i + g]);       // row r0
        const u64 iq1 = splat2(invc[64 * wc + 16 * i + g + 8]);   // row r0+8
        #pragma unroll
        for (int j = 0; j < 4; j++) {
            #pragma unroll
            for (int h = 0; h < 2; h++) {
                u64 pr = pack2(c[i][j][2 * h], c[i][j][2 * h + 1]);
                u64 x = fmul2(pr, h ? iq1 : iq0);   // dot/(4*conc), in [-0.55,0.55]
                u64 p = ffma2(x, k6, k5);
                p = ffma2(x, p, k4);
                p = ffma2(x, p, k3);
                p = ffma2(x, p, k2);
                p = ffma2(x, p, one);
                p = ffma2(x, p, one);
                p = fmul2(p, p);
                p = fmul2(p, p);                    // e^{dot/conc}
                colsum[j] = fadd2(colsum[j], p);
            }
        }
    }
    // butterfly over the 8 row-groups (lanes with equal lane%4)
    #pragma unroll
    for (int mask = 4; mask <= 16; mask <<= 1)
        #pragma unroll
        for (int j = 0; j < 4; j++)
            colsum[j] = fadd2(colsum[j], shfl_xor2(colsum[j], mask));

    float* sacc = (float*)(smem + SMEM_SACC);
    if (lane < 4) {
        #pragma unroll
        for (int j = 0; j < 4; j++) {
            float2 v; v.x = __uint_as_float((uint32_t)colsum[j]);
            v.y = __uint_as_float((uint32_t)(colsum[j] >> 32));
            *(float2*)&sacc[wid * 32 + 8 * j + 2 * lane] = v;     // cols (2*lane, +1) of n-tile j
        }
    }
    __syncthreads();

    if (tid < TB) {
        int wb2 = tid >> 5, lc = tid & 31;
        float s = sacc[wb2 * 32 + lc] + sacc[(wb2 + 4) * 32 + lc];   // wc=0 + wc=1
        atomicAdd(&g_S[z * BATCH + bT * TB + tid], s);
    }
}

// Finalize pass 1: 24 blocks x 256 threads, one (branch,m,b) item per thread.
// Deterministic in-block reduction -> g_part[block].
__global__ void finalize1_kernel(const float* __restrict__ cen,  const float* __restrict__ cenI,
                                 const float* __restrict__ f,    const float* __restrict__ fI,
                                 const float* __restrict__ conc, const float* __restrict__ concI,
                                 const int* __restrict__ lab,    const int* __restrict__ labI)
{
    __shared__ float sred[FIN_THREADS];
    const int tid = threadIdx.x;
    const int idx = blockIdx.x * FIN_THREADS + tid;   // 0..6143

    int branch = idx / (MNUM * BATCH);
    int r = idx - branch * MNUM * BATCH;
    int m = r / BATCH;
    int b = r - m * BATCH;

    const float* cenP  = branch ? cenI  : cen;
    const float* featP = branch ? f     : fI;
    const float* concP = branch ? concI : conc;
    const int*   labP  = branch ? labI  : lab;

    int cidx = labP[m * BATCH + b];
    const float4* cr = (const float4*)(cenP + ((size_t)(m * CNUM) + cidx) * DDIM);
    const float4* fr = (const float4*)(featP + (size_t)b * DDIM);
    float dot = 0.0f;
    #pragma unroll
    for (int d = 0; d < 16; d++) {
        float4 a = cr[d];
        float4 w = fr[d];
        dot += a.x * w.x + a.y * w.y + a.z * w.z + a.w * w.w;
    }
    float logit = dot / concP[m * CNUM + cidx];
    sred[tid] = logit - logf(g_S[idx]);     // log(pos/sum) = logit_pos - log(S)
    __syncthreads();
    #pragma unroll
    for (int s = FIN_THREADS / 2; s > 0; s >>= 1) {
        if (tid < s) sred[tid] += sred[tid + s];
        __syncthreads();
    }
    if (tid == 0) g_part[blockIdx.x] = sred[0];
}

// Finalize pass 2: one warp, deterministic.
__global__ void finalize2_kernel(const int* __restrict__ lb, float* __restrict__ out)
{
    if (threadIdx.x == 0) {
        float s = 0.0f;
        #pragma unroll
        for (int i = 0; i < FIN_BLOCKS; i++) s += g_part[i];
        float scale = -(float)lb[0] / (2.0f * (float)BATCH * (float)MNUM);
        out[0] = scale * s;
    }
}

extern "C" void kernel_launch(void* const* d_in, const int* in_sizes, int n_in,
                              void* d_out, int out_size)
{
    const float* f     = (const float*)d_in[0];
    const float* fI    = (const float*)d_in[1];
    const float* cen   = (const float*)d_in[2];
    const float* cenI  = (const float*)d_in[3];
    const float* conc  = (const float*)d_in[4];
    const float* concI = (const float*)d_in[5];
    const int*   lab   = (const int*)d_in[6];
    const int*   labI  = (const int*)d_in[7];
    const int*   lb    = (const int*)d_in[8];
    float* out = (float*)d_out;

    int convN = 2 * CEN4 + 2 * FEAT4;
    convert_kernel<<<(convN + 255) / 256, 256>>>(cen, cenI, f, fI);
    dim3 grid(CNUM / TC, BATCH / TB, NBR * MNUM);
    mma_exp_kernel<<<grid, 256, SMEM_TOTAL>>>(conc, concI);
    finalize1_kernel<<<FIN_BLOCKS, FIN_THREADS>>>(cen, cenI, f, fI, conc, concI, lab, labI);
    finalize2_kernel<<<1, 32>>>(lb, out);
}